// round 8
// baseline (speedup 1.0000x reference)
#include <cuda_runtime.h>
#include <math_constants.h>
#include <cstdint>

// Problem constants (fixed by setup_inputs)
#define BB 8
#define NN 2048
#define MM 2048
#define DD 256
#define KSIM 16
#define KCOOR 4

// ---------------- device scratch (allocation-free) ----------------
__device__ float g_f1n[(size_t)BB * NN * DD];
__device__ float g_f2n[(size_t)BB * MM * DD];
__device__ float g_w[(size_t)BB * MM * NN];   // xla-exp(w1)
__device__ float g_den1[(size_t)BB * NN];
__device__ float g_den2[(size_t)BB * MM];

// ---------------- accurate-class expf replica (XLA:CPU / Eigen / Cephes) ----------------
// Proven bit-equivalent across fused/unfused variants for our argument range.
__device__ __forceinline__ float xla_expf(float x) {
    const float exp_hi = 88.3762626647950f;
    const float exp_lo = -88.3762626647949f;
    const float LOG2EF = 1.44269504088896341f;
    const float C1     = 0.693359375f;
    const float C2     = -2.12194440e-4f;
    const float p0     = 1.9875691500e-4f;
    const float p1     = 1.3981999507e-3f;
    const float p2     = 8.3334519073e-3f;
    const float p3     = 4.1665795894e-2f;
    const float p4     = 1.6666665459e-1f;
    const float p5     = 5.0000001201e-1f;

    x = fminf(x, exp_hi);
    x = fmaxf(x, exp_lo);

    float fx = floorf(fmaf(x, LOG2EF, 0.5f));

    float tmp = __fmul_rn(C1, fx);
    float z   = __fmul_rn(C2, fx);
    float r   = __fsub_rn(x, tmp);
    r = __fsub_rn(r, z);

    float r2 = __fmul_rn(r, r);

    float y = p0;
    y = fmaf(y, r, p1);
    y = fmaf(y, r, p2);
    y = fmaf(y, r, p3);
    y = fmaf(y, r, p4);
    y = fmaf(y, r, p5);
    y = fmaf(y, r2, r);
    y = __fadd_rn(y, 1.0f);

    int n = (int)fx;
    float pow2n = __int_as_float((n + 127) << 23);
    return __fmul_rn(y, pow2n);
}

// ---------------- argmax helper (desc value, tie -> smaller index) ----------------
__device__ __forceinline__ void amx(float& bv, int& bi, float v2, int i2) {
    if (v2 > bv || (v2 == bv && i2 < bi)) { bv = v2; bi = i2; }
}

// ---------------- kernel 1a: per-row norms, XLA:CPU sharded-vector reduce replica ----
// 16-lane accumulator (4 shards of <4 x float>), contiguous 16-wide strides over the
// row; shard combine (S0+S1)+(S2+S3); halving shuffle reduce (V0+V2)+(V1+V3).
// All mul/add strictly separate rounds (XLA:CPU emits unfused IR for fused reduce input).
__global__ void row_norms(const float* __restrict__ in, float* __restrict__ den, int rows) {
    int r = blockIdx.x * blockDim.x + threadIdx.x;
    if (r >= rows) return;
    const float* v = in + (size_t)r * DD;

    float s[16];
    #pragma unroll
    for (int l = 0; l < 16; l++) s[l] = 0.f;

    for (int t = 0; t < DD; t += 16) {
        #pragma unroll
        for (int l = 0; l < 16; l++) {
            float x = v[t + l];
            s[l] = __fadd_rn(s[l], __fmul_rn(x, x));
        }
    }

    // pairwise shard combine: V[l] = (s[l]+s[4+l]) + (s[8+l]+s[12+l])
    float V[4];
    #pragma unroll
    for (int l = 0; l < 4; l++)
        V[l] = __fadd_rn(__fadd_rn(s[l], s[4 + l]), __fadd_rn(s[8 + l], s[12 + l]));

    // halving shuffle reduce over <4 x float>: (V0+V2) + (V1+V3)
    float total = __fadd_rn(__fadd_rn(V[0], V[2]), __fadd_rn(V[1], V[3]));

    den[r] = fmaxf(sqrtf(total), 1e-8f);
}

// ---------------- kernel 1b: elementwise divide ----------------
__global__ void div_rows(const float* __restrict__ in, const float* __restrict__ den,
                         float* __restrict__ out) {
    int row = blockIdx.x;
    float d = den[row];
    out[(size_t)row * DD + threadIdx.x] = __fdiv_rn(in[(size_t)row * DD + threadIdx.x], d);
}

// ---------------- kernel 2: batched NT-SGEMM, sequential-k FFMA chain, xla-exp epilogue ----------------
#define GBM 128
#define GBN 128
#define GBK 8
#define GTM 8
#define GTN 8
__global__ __launch_bounds__(256, 2)
void gemm_exp(const float* __restrict__ A, const float* __restrict__ Bm,
              float* __restrict__ C) {
    const int b  = blockIdx.z;
    const int bm = blockIdx.y * GBM;
    const int bn = blockIdx.x * GBN;
    const float* Ab = A  + (size_t)b * MM * DD;
    const float* Bb = Bm + (size_t)b * NN * DD;
    float*       Cb = C  + (size_t)b * MM * NN;

    __shared__ float As[GBK][GBM];
    __shared__ float Bs[GBK][GBN];

    const int tid = threadIdx.x;
    const int ty  = tid / 16;
    const int tx  = tid % 16;
    const int lrow = tid >> 1;
    const int lk4  = (tid & 1) * 4;

    float acc[GTM][GTN];
    #pragma unroll
    for (int i = 0; i < GTM; i++)
        #pragma unroll
        for (int j = 0; j < GTN; j++) acc[i][j] = 0.f;

    for (int k0 = 0; k0 < DD; k0 += GBK) {
        float4 a4 = *(const float4*)(Ab + (size_t)(bm + lrow) * DD + k0 + lk4);
        float4 b4 = *(const float4*)(Bb + (size_t)(bn + lrow) * DD + k0 + lk4);
        __syncthreads();
        As[lk4 + 0][lrow] = a4.x; As[lk4 + 1][lrow] = a4.y;
        As[lk4 + 2][lrow] = a4.z; As[lk4 + 3][lrow] = a4.w;
        Bs[lk4 + 0][lrow] = b4.x; Bs[lk4 + 1][lrow] = b4.y;
        Bs[lk4 + 2][lrow] = b4.z; Bs[lk4 + 3][lrow] = b4.w;
        __syncthreads();
        #pragma unroll
        for (int k = 0; k < GBK; k++) {      // global k strictly ascending
            float ar[GTM], br[GTN];
            #pragma unroll
            for (int i = 0; i < GTM; i += 4) {
                float4 t = *(const float4*)&As[k][ty * GTM + i];
                ar[i] = t.x; ar[i+1] = t.y; ar[i+2] = t.z; ar[i+3] = t.w;
            }
            #pragma unroll
            for (int j = 0; j < GTN; j += 4) {
                float4 t = *(const float4*)&Bs[k][tx * GTN + j];
                br[j] = t.x; br[j+1] = t.y; br[j+2] = t.z; br[j+3] = t.w;
            }
            #pragma unroll
            for (int i = 0; i < GTM; i++)
                #pragma unroll
                for (int j = 0; j < GTN; j++)
                    acc[i][j] = fmaf(ar[i], br[j], acc[i][j]);  // single-acc chain
        }
    }

    #pragma unroll
    for (int i = 0; i < GTM; i++) {
        size_t rowoff = (size_t)(bm + ty * GTM + i) * NN + bn + tx * GTN;
        #pragma unroll
        for (int j = 0; j < GTN; j += 4) {
            float4 o;
            o.x = xla_expf(acc[i][j + 0]);
            o.y = xla_expf(acc[i][j + 1]);
            o.z = xla_expf(acc[i][j + 2]);
            o.w = xla_expf(acc[i][j + 3]);
            *(float4*)(Cb + rowoff + j) = o;
        }
    }
}

// ---------------- kernel 3: fused row kernel (bit-replica selection) ----------------
__global__ __launch_bounds__(256)
void row_topk(const float* __restrict__ w_in, const float* __restrict__ f1,
              const float* __restrict__ p, const float* __restrict__ q,
              float* __restrict__ f_out, float* __restrict__ idx_out,
              float* __restrict__ w_out) {
    const int m = blockIdx.x;
    const int b = blockIdx.y;
    const int tid  = threadIdx.x;   // 256
    const int lane = tid & 31;
    const int wid  = tid >> 5;

    __shared__ float ws[NN];
    __shared__ float w2s[NN];
    __shared__ float sv[8];
    __shared__ int   si[8];
    __shared__ int   sel[KSIM];

    const size_t rowbase = ((size_t)b * MM + m) * NN;

    for (int n = tid; n < NN; n += 256) ws[n] = w_in[rowbase + n];

    const float qx = q[((size_t)b * MM + m) * 3 + 0];
    const float qy = q[((size_t)b * MM + m) * 3 + 1];
    const float qz = q[((size_t)b * MM + m) * 3 + 2];
    const float qq = __fadd_rn(__fadd_rn(__fmul_rn(qx, qx), __fmul_rn(qy, qy)),
                               __fmul_rn(qz, qz));
    for (int n = tid; n < NN; n += 256) {
        const float px = p[((size_t)b * NN + n) * 3 + 0];
        const float py = p[((size_t)b * NN + n) * 3 + 1];
        const float pz = p[((size_t)b * NN + n) * 3 + 2];
        const float pp = __fadd_rn(__fadd_rn(__fmul_rn(px, px), __fmul_rn(py, py)),
                                   __fmul_rn(pz, pz));
        // Eigen gebp k=3 fused pmadd chain: fma(qz,pz, fma(qy,py, qx*px))
        const float dot3 = fmaf(qz, pz, fmaf(qy, py, __fmul_rn(qx, px)));
        const float d2 = __fsub_rn(__fadd_rn(qq, pp), __fmul_rn(2.0f, dot3));
        w2s[n] = xla_expf(-d2);
    }
    __syncthreads();

    // top-4 of w2 (tie -> smaller index); scatter-add into ws
    for (int t = 0; t < KCOOR; t++) {
        float bv = -CUDART_INF_F; int bi = 1 << 30;
        for (int n = tid; n < NN; n += 256) amx(bv, bi, w2s[n], n);
        #pragma unroll
        for (int o = 16; o > 0; o >>= 1) {
            float v2 = __shfl_xor_sync(0xffffffffu, bv, o);
            int   i2 = __shfl_xor_sync(0xffffffffu, bi, o);
            amx(bv, bi, v2, i2);
        }
        if (lane == 0) { sv[wid] = bv; si[wid] = bi; }
        __syncthreads();
        if (tid == 0) {
            float fv = sv[0]; int fi = si[0];
            #pragma unroll
            for (int i = 1; i < 8; i++) amx(fv, fi, sv[i], si[i]);
            ws[fi] = __fadd_rn(ws[fi], fv);
            w2s[fi] = -CUDART_INF_F;
        }
        __syncthreads();
    }

    if (w_out) {
        for (int n = tid; n < NN; n += 256) w_out[rowbase + n] = ws[n];
        __syncthreads();
    }

    // top-16 of ws (tie -> smaller index), destructive
    for (int t = 0; t < KSIM; t++) {
        float bv = -CUDART_INF_F; int bi = 1 << 30;
        for (int n = tid; n < NN; n += 256) amx(bv, bi, ws[n], n);
        #pragma unroll
        for (int o = 16; o > 0; o >>= 1) {
            float v2 = __shfl_xor_sync(0xffffffffu, bv, o);
            int   i2 = __shfl_xor_sync(0xffffffffu, bi, o);
            amx(bv, bi, v2, i2);
        }
        if (lane == 0) { sv[wid] = bv; si[wid] = bi; }
        __syncthreads();
        if (tid == 0) {
            float fv = sv[0]; int fi = si[0];
            #pragma unroll
            for (int i = 1; i < 8; i++) amx(fv, fi, sv[i], si[i]);
            sel[t] = fi;
            ws[fi] = -CUDART_INF_F;
        }
        __syncthreads();
    }

    if (idx_out && tid < KSIM)
        idx_out[((size_t)b * MM + m) * KSIM + tid] = (float)sel[tid];

    if (f_out) {
        const int d = tid;   // DD == 256 == blockDim
        float s = 0.f, mx = -CUDART_INF_F;
        #pragma unroll
        for (int k = 0; k < KSIM; k++) {
            float v = f1[((size_t)b * NN + sel[k]) * DD + d];
            s += v;
            mx = fmaxf(mx, v);
        }
        size_t fo = ((size_t)b * MM + m) * (2 * DD);
        f_out[fo + d]      = s * (1.0f / 16.0f);
        f_out[fo + DD + d] = mx;
    }
}

// ---------------- launch ----------------
extern "C" void kernel_launch(void* const* d_in, const int* in_sizes, int n_in,
                              void* d_out, int out_size) {
    const float* f1 = (const float*)d_in[0];
    const float* f2 = (const float*)d_in[1];
    const float* p  = (const float*)d_in[2];
    const float* q  = (const float*)d_in[3];

    float* f1n;  cudaGetSymbolAddress((void**)&f1n,  g_f1n);
    float* f2n;  cudaGetSymbolAddress((void**)&f2n,  g_f2n);
    float* wbuf; cudaGetSymbolAddress((void**)&wbuf, g_w);
    float* den1; cudaGetSymbolAddress((void**)&den1, g_den1);
    float* den2; cudaGetSymbolAddress((void**)&den2, g_den2);

    const size_t F_E = (size_t)BB * MM * (2 * DD);
    const size_t I_E = (size_t)BB * MM * KSIM;
    const size_t W_E = (size_t)BB * MM * NN;

    float* out = (float*)d_out;
    float* f_out = nullptr; float* idx_out = nullptr; float* w_out = nullptr;
    size_t osz = (size_t)out_size;
    if (osz >= F_E + I_E + W_E) {
        f_out = out; idx_out = out + F_E; w_out = out + F_E + I_E;
    } else if (osz == F_E + I_E) {
        f_out = out; idx_out = out + F_E;
    } else if (osz == W_E) {
        w_out = out;
    } else {
        f_out = out;
    }

    row_norms<<<(BB * NN + 255) / 256, 256>>>(f1, den1, BB * NN);
    row_norms<<<(BB * MM + 255) / 256, 256>>>(f2, den2, BB * MM);
    div_rows<<<BB * NN, 256>>>(f1, den1, f1n);
    div_rows<<<BB * MM, 256>>>(f2, den2, f2n);

    dim3 ggrid(NN / GBN, MM / GBM, BB);
    gemm_exp<<<ggrid, 256>>>(f2n, f1n, wbuf);

    dim3 rgrid(MM, BB);
    row_topk<<<rgrid, 256>>>(wbuf, f1, p, q, f_out, idx_out, w_out);
}